// round 17
// baseline (speedup 1.0000x reference)
#include <cuda_runtime.h>
#include <cstdint>
#include <cstddef>

#define NB        16
#define NPTS      131072
#define NSAMP     4096
#define CLUSTER_X 8
#define PTS_CTA   (NPTS / CLUSTER_X)      // 16384
#define NTHREADS  1024
#define NWARPS    (NTHREADS / 32)         // 32
#define PTS_THR   (PTS_CTA / NTHREADS)    // 16

#define XY_BYTES    (PTS_CTA * 8)         // float2 x,y : 131072
#define Z_BYTES     (PTS_CTA * 4)         // float  z   : 65536
#define WARPRED_OFF (XY_BYTES + Z_BYTES)  // 196608
#define CRED_OFF    (WARPRED_OFF + NWARPS * 8)
#define SLOT_BYTES  32                    // key(8) + x,y,z(12) + pad
#define SMEM_TOTAL  (CRED_OFF + 2 * CLUSTER_X * SLOT_BYTES)

__device__ __forceinline__ unsigned smem_u32(const void* p) {
    return (unsigned)__cvta_generic_to_shared(p);
}

__global__ void __launch_bounds__(NTHREADS, 1) __cluster_dims__(CLUSTER_X, 1, 1)
fps_cluster(const float* __restrict__ xyz, float* __restrict__ out)
{
    extern __shared__ char smem[];
    float2* sxy = (float2*)smem;                       // [x,y] pairs
    float*  sz  = (float*)(smem + XY_BYTES);           // z
    unsigned long long* warpRed = (unsigned long long*)(smem + WARPRED_OFF);
    char* cred = smem + CRED_OFF;

    const int tid  = threadIdx.x;
    const int rank = blockIdx.x & (CLUSTER_X - 1);
    const int b    = blockIdx.x >> 3;
    const int wid  = tid >> 5;
    const int lane = tid & 31;

    // Stage this CTA's 16384 points into SMEM (xy pairs + z plane).
    const float* bbase = xyz + (size_t)b * NPTS * 3 + (size_t)rank * PTS_CTA * 3;
    for (int j = tid; j < PTS_CTA; j += NTHREADS) {
        sxy[j] = make_float2(bbase[3 * j + 0], bbase[3 * j + 1]);
        sz[j]  = bbase[3 * j + 2];
    }

    // Per-point running min-distance in registers (16 per thread).
    float dmin[PTS_THR];
#pragma unroll
    for (int i = 0; i < PTS_THR; i++) dmin[i] = __int_as_float(0x7f800000);

    // First centroid = point 0 of the batch.
    const float* b0 = xyz + (size_t)b * NPTS * 3;
    float cx = __ldg(b0 + 0), cy = __ldg(b0 + 1), cz = __ldg(b0 + 2);

    if (rank == 0 && tid == 0) out[b * NSAMP] = 0.0f;   // float output
    __syncthreads();

    for (int k = 0; k < NSAMP - 1; ++k) {
        // ---- scan 16 points/thread from SMEM (verified FMA arithmetic) ----
        float bestVal = -1.0f;
        int   bestIdx = 0;
#pragma unroll
        for (int i = 0; i < PTS_THR; i++) {
            int p = i * NTHREADS + tid;
            float2 xy = sxy[p];
            float  zz = sz[p];
            float dx = __fsub_rn(xy.x, cx);
            float dy = __fsub_rn(xy.y, cy);
            float dz = __fsub_rn(zz,   cz);
            float d  = __fmaf_rn(dz, dz, __fmaf_rn(dy, dy, __fmul_rn(dx, dx)));
            float dm = fminf(dmin[i], d);
            dmin[i]  = dm;
            if (dm > bestVal) { bestVal = dm; bestIdx = p; }  // strict >: lowest p wins
        }

        unsigned gidx = (unsigned)(rank * PTS_CTA + bestIdx);
        unsigned long long key =
            ((unsigned long long)__float_as_uint(bestVal) << 32) |
            (unsigned long long)(0xFFFFFFFFu - gidx);

        // ---- warp reduce ----
#pragma unroll
        for (int o = 16; o; o >>= 1) {
            unsigned long long other = __shfl_xor_sync(0xFFFFFFFFu, key, o);
            if (other > key) key = other;
        }
        if (lane == 0) warpRed[wid] = key;
        __syncthreads();

        const int par = k & 1;

        // ---- block reduce (32 warp winners) + publish to all 8 CTAs ----
        if (wid == 0) {
            unsigned long long bk = warpRed[lane];     // exactly 32 warps
#pragma unroll
            for (int o = 16; o; o >>= 1) {
                unsigned long long other = __shfl_xor_sync(0xFFFFFFFFu, bk, o);
                if (other > bk) bk = other;
            }
            unsigned widx  = 0xFFFFFFFFu - (unsigned)(bk & 0xFFFFFFFFull);
            int      local = (int)(widx & (PTS_CTA - 1));
            float2 wxy = sxy[local];
            float  wz  = sz[local];

            if (lane < CLUSTER_X) {
                unsigned slot = smem_u32(cred) +
                                (unsigned)(par * CLUSTER_X * SLOT_BYTES + rank * SLOT_BYTES);
                unsigned raddr;
                asm volatile("mapa.shared::cluster.u32 %0, %1, %2;"
                             : "=r"(raddr) : "r"(slot), "r"(lane));
                asm volatile("st.shared::cluster.u64 [%0], %1;"
                             :: "r"(raddr), "l"(bk) : "memory");
                asm volatile("st.shared::cluster.v2.f32 [%0], {%1, %2};"
                             :: "r"(raddr + 8), "f"(wxy.x), "f"(wxy.y) : "memory");
                asm volatile("st.shared::cluster.f32 [%0], %1;"
                             :: "r"(raddr + 16), "f"(wz) : "memory");
            }
        }

        // One cluster barrier per iteration (double-buffered slots).
        asm volatile("barrier.cluster.arrive.aligned;" ::: "memory");
        asm volatile("barrier.cluster.wait.aligned;"   ::: "memory");

        // ---- every thread reduces the 8 candidates locally (broadcast LDS) ----
        const char* cp = cred + par * CLUSTER_X * SLOT_BYTES;
        unsigned long long bk = 0ull;
        float wx = 0.f, wy = 0.f, wz = 0.f;
#pragma unroll
        for (int r = 0; r < CLUSTER_X; r++) {
            unsigned long long kk = *(const unsigned long long*)(cp + r * SLOT_BYTES);
            float xx = *(const float*)(cp + r * SLOT_BYTES + 8);
            float yy = *(const float*)(cp + r * SLOT_BYTES + 12);
            float zzc = *(const float*)(cp + r * SLOT_BYTES + 16);
            if (kk > bk) { bk = kk; wx = xx; wy = yy; wz = zzc; }
        }
        cx = wx; cy = wy; cz = wz;

        if (rank == 0 && tid == 0)
            out[b * NSAMP + k + 1] =
                (float)(0xFFFFFFFFu - (unsigned)(bk & 0xFFFFFFFFull));
    }
}

extern "C" void kernel_launch(void* const* d_in, const int* in_sizes, int n_in,
                              void* d_out, int out_size)
{
    (void)in_sizes; (void)n_in; (void)out_size;
    const float* xyz = (const float*)d_in[0];
    float* out = (float*)d_out;

    cudaFuncSetAttribute(fps_cluster, cudaFuncAttributeMaxDynamicSharedMemorySize,
                         SMEM_TOTAL);

    dim3 grid(NB * CLUSTER_X);   // 128 CTAs = 16 clusters of 8
    dim3 block(NTHREADS);
    fps_cluster<<<grid, block, SMEM_TOTAL>>>(xyz, out);
}